// round 12
// baseline (speedup 1.0000x reference)
#include <cuda_runtime.h>

#define D 128
#define N_ING 100000
#define N_TASTE 50000
#define E_EDGES 600000
#define NEG_SLOPE 0.2f
#define CAP 64          // per-dst bucket capacity; deg ~ Poisson(12), P(>64) < 1e-20

// ---------------- scratch (device globals) ----------------
__device__ float  g_v_src[D];
__device__ float  g_v_dst[D];
__device__ float  g_c_src, g_c_dst;
__device__ float  g_a_src[N_ING];
__device__ int    g_cnt[N_TASTE];                  // degree cursor / epilogue mask
__device__ int    g_srcslot[(size_t)N_TASTE * CAP];// src index buckets
__device__ float2 g_wpk[D * D];                    // W packed (hi, lo) tf32 parts
__device__ float  g_gbuf[(size_t)N_TASTE * D];     // aggregated rows (25.6MB)

// ---------------- tf32 helpers ----------------
__device__ __forceinline__ void split_tf32(float x, unsigned& hi, unsigned& lo) {
    asm("cvt.rna.tf32.f32 %0, %1;" : "=r"(hi) : "f"(x));
    float lof = x - __uint_as_float(hi);
    asm("cvt.rna.tf32.f32 %0, %1;" : "=r"(lo) : "f"(lof));
}
__device__ __forceinline__ void mma_tf32(float* c,
                                         unsigned a0, unsigned a1, unsigned a2, unsigned a3,
                                         unsigned b0, unsigned b1) {
    asm volatile("mma.sync.aligned.m16n8k8.row.col.f32.tf32.tf32.f32 "
                 "{%0,%1,%2,%3}, {%4,%5,%6,%7}, {%8,%9}, {%0,%1,%2,%3};"
                 : "+f"(c[0]), "+f"(c[1]), "+f"(c[2]), "+f"(c[3])
                 : "r"(a0), "r"(a1), "r"(a2), "r"(a3), "r"(b0), "r"(b1));
}

// ---------------- K0: warp-per-row  v = W @ att  (+ bias dots) -------------
__global__ void k0_prep(const float* __restrict__ W_ing,  const float* __restrict__ b_ing,
                        const float* __restrict__ W_taste,const float* __restrict__ b_taste,
                        const float* __restrict__ att_src,const float* __restrict__ att_dst) {
    int w    = (blockIdx.x * blockDim.x + threadIdx.x) >> 5;
    int lane = threadIdx.x & 31;
    if (w >= 258) return;
    const float* vecA;
    const float* vecB;
    if (w < 128)      { vecA = W_ing   + w * D;         vecB = att_src; }
    else if (w < 256) { vecA = W_taste + (w - 128) * D; vecB = att_dst; }
    else if (w == 256){ vecA = b_ing;                   vecB = att_src; }
    else              { vecA = b_taste;                 vecB = att_dst; }
    float4 a = ((const float4*)vecA)[lane];
    float4 c = ((const float4*)vecB)[lane];
    float s = a.x * c.x + a.y * c.y + a.z * c.z + a.w * c.w;
    #pragma unroll
    for (int o = 16; o; o >>= 1) s += __shfl_down_sync(0xffffffffu, s, o);
    if (lane == 0) {
        if (w < 128)       g_v_src[w] = s;
        else if (w < 256)  g_v_dst[w - 128] = s;
        else if (w == 256) g_c_src = s;
        else               g_c_dst = s;
    }
}

// ---------------- a_src only: 4 rows/warp over N_ING ----------------
__global__ void k_asrc(const float* __restrict__ x_ing) {
    int warp = (blockIdx.x * blockDim.x + threadIdx.x) >> 5;
    int lane = threadIdx.x & 31;
    int row0 = warp * 4;
    if (row0 >= N_ING) return;
    const float4* x4 = (const float4*)x_ing;
    float4 vv = ((const float4*)g_v_src)[lane];
    float  cc = g_c_src;
    float4 xv[4];
    #pragma unroll
    for (int r = 0; r < 4; r++) xv[r] = x4[(size_t)(row0 + r) * 32 + lane];
    #pragma unroll
    for (int r = 0; r < 4; r++) {
        float s = xv[r].x * vv.x + xv[r].y * vv.y + xv[r].z * vv.z + xv[r].w * vv.w;
        #pragma unroll
        for (int o = 16; o; o >>= 1) s += __shfl_down_sync(0xffffffffu, s, o);
        if (lane == 0) g_a_src[row0 + r] = s + cc;
    }
}

// ---------------- stream B: split W, zero counters, fill, out_ing copy -----
__global__ void k_splitW(const float* __restrict__ W) {
    int i = blockIdx.x * blockDim.x + threadIdx.x;
    if (i >= D * D) return;
    unsigned hi, lo;
    split_tf32(W[i], hi, lo);
    g_wpk[i] = make_float2(__uint_as_float(hi), __uint_as_float(lo));
}

__global__ void k_zero() {
    int i = blockIdx.x * blockDim.x + threadIdx.x;
    if (i < N_TASTE) g_cnt[i] = 0;
}

// fill depends ONLY on src/dst (no logits) -> stream B, parallel with k0/asrc
__global__ void k_fill(const int* __restrict__ src, const int* __restrict__ dst) {
    int e = blockIdx.x * blockDim.x + threadIdx.x;
    if (e >= E_EDGES) return;
    int t = dst[e];
    int pos = atomicAdd(&g_cnt[t], 1);          // pos < CAP w.h.p. (Poisson tail)
    g_srcslot[(size_t)t * CAP + pos] = src[e];
}

__global__ void k_copy(const float4* __restrict__ src, float4* __restrict__ dst) {
    int i = blockIdx.x * blockDim.x + threadIdx.x;
    int n = N_ING * 32;
    int stride = gridDim.x * blockDim.x;
    for (; i < n; i += stride) dst[i] = src[i];
}

// ---------------- k_agg: softmax-agg; a_src via uniform scalar LDG ---------
// warp per dst; a_dst folded per-segment (one butterfly per dst).
__global__ void __launch_bounds__(256) k_agg(const float* __restrict__ x_ing,
                                             const float* __restrict__ x_taste) {
    int gw    = (blockIdx.x * blockDim.x + threadIdx.x) >> 5;
    int lane  = threadIdx.x & 31;
    int nwarp = (gridDim.x * blockDim.x) >> 5;
    const float4* x4  = (const float4*)x_ing;
    const float4* xt4 = (const float4*)x_taste;
    float4* gb4 = (float4*)g_gbuf;
    float4 vd = ((const float4*)g_v_dst)[lane];
    float  cd = g_c_dst;

    for (int t = gw; t < N_TASTE; t += nwarp) {
        int n = g_cnt[t];
        float4 acc = make_float4(0.f, 0.f, 0.f, 0.f);
        float wsum = 0.f;
        if (n > 0) {
            // a_dst for this segment (one butterfly per dst; all lanes get it)
            float4 xt = xt4[(size_t)t * 32 + lane];
            float ad = xt.x*vd.x + xt.y*vd.y + xt.z*vd.z + xt.w*vd.w;
            #pragma unroll
            for (int o = 16; o; o >>= 1) ad += __shfl_xor_sync(0xffffffffu, ad, o);
            float base = ad + cd;

            const int* sp = g_srcslot + (size_t)t * CAP;
            int e = 0;
            for (; e + 4 <= n; e += 4) {
                int s0 = sp[e], s1 = sp[e+1], s2 = sp[e+2], s3 = sp[e+3];
                float4 v0 = x4[(size_t)s0 * 32 + lane];
                float4 v1 = x4[(size_t)s1 * 32 + lane];
                float4 v2 = x4[(size_t)s2 * 32 + lane];
                float4 v3 = x4[(size_t)s3 * 32 + lane];
                float l0 = g_a_src[s0] + base;     // uniform scalar LDG (L2-hit)
                float l1 = g_a_src[s1] + base;
                float l2 = g_a_src[s2] + base;
                float l3 = g_a_src[s3] + base;
                l0 = l0 > 0.f ? l0 : NEG_SLOPE * l0;
                l1 = l1 > 0.f ? l1 : NEG_SLOPE * l1;
                l2 = l2 > 0.f ? l2 : NEG_SLOPE * l2;
                l3 = l3 > 0.f ? l3 : NEG_SLOPE * l3;
                float w0 = __expf(l0), w1 = __expf(l1), w2 = __expf(l2), w3 = __expf(l3);
                wsum  += w0 + w1 + w2 + w3;
                acc.x += w0*v0.x + w1*v1.x + w2*v2.x + w3*v3.x;
                acc.y += w0*v0.y + w1*v1.y + w2*v2.y + w3*v3.y;
                acc.z += w0*v0.z + w1*v1.z + w2*v2.z + w3*v3.z;
                acc.w += w0*v0.w + w1*v1.w + w2*v2.w + w3*v3.w;
            }
            for (; e < n; e++) {
                int si = sp[e];
                float4 v = x4[(size_t)si * 32 + lane];
                float l = g_a_src[si] + base;
                l = l > 0.f ? l : NEG_SLOPE * l;
                float w = __expf(l);
                wsum += w;
                acc.x += w*v.x; acc.y += w*v.y; acc.z += w*v.z; acc.w += w*v.w;
            }
        }
        float inv = 1.f / (wsum + 1e-16f);
        acc.x *= inv; acc.y *= inv; acc.z *= inv; acc.w *= inv;
        gb4[(size_t)t * 32 + lane] = acc;
    }
}

// ---------------- k_gemm: TF32 3-pass MMA, packed W(hi,lo) in smem ---------
// TM=128 rows/block, warp owns 16 rows x 128 cols (validated mapping).
#define TM 128
#define SROW 132
__global__ void __launch_bounds__(256) k_gemm(const float* __restrict__ bias,
                                              const float* __restrict__ x_taste,
                                              float* __restrict__ out_taste) {
    extern __shared__ float2 wpk[];     // [128][SROW] packed (hi,lo)
    int tid  = threadIdx.x;
    int lane = tid & 31;
    int wrp  = tid >> 5;
    int row0 = blockIdx.x * TM;

    for (int i = tid; i < D * D; i += 256) {
        int k = i >> 7, n = i & 127;
        wpk[k * SROW + n] = g_wpk[i];
    }
    __syncthreads();

    int g = lane >> 2, t4 = lane & 3;
    int rbase = wrp * 16;
    int r0 = row0 + rbase + g;
    int r1 = r0 + 8;
    bool v0 = r0 < N_TASTE, v1 = r1 < N_TASTE;
    const float* A0 = g_gbuf + (size_t)(v0 ? r0 : 0) * D;
    const float* A1 = g_gbuf + (size_t)(v1 ? r1 : 0) * D;

    float acc[16][4];
    #pragma unroll
    for (int nn = 0; nn < 16; nn++)
        #pragma unroll
        for (int j = 0; j < 4; j++) acc[nn][j] = 0.f;

    #pragma unroll 1
    for (int kk = 0; kk < 16; kk++) {
        int k0 = kk * 8;
        float a0f = v0 ? A0[k0 + t4    ] : 0.f;
        float a2f = v0 ? A0[k0 + t4 + 4] : 0.f;
        float a1f = v1 ? A1[k0 + t4    ] : 0.f;
        float a3f = v1 ? A1[k0 + t4 + 4] : 0.f;
        unsigned a0h,a0l,a1h,a1l,a2h,a2l,a3h,a3l;
        split_tf32(a0f, a0h, a0l);
        split_tf32(a1f, a1h, a1l);
        split_tf32(a2f, a2h, a2l);
        split_tf32(a3f, a3h, a3l);
        #pragma unroll
        for (int nn = 0; nn < 16; nn++) {
            int col = nn * 8 + g;
            float2 b0 = wpk[(k0 + t4    ) * SROW + col];   // LDS.64: (hi, lo)
            float2 b1 = wpk[(k0 + t4 + 4) * SROW + col];
            unsigned b0h = __float_as_uint(b0.x), b0l = __float_as_uint(b0.y);
            unsigned b1h = __float_as_uint(b1.x), b1l = __float_as_uint(b1.y);
            mma_tf32(acc[nn], a0h,a1h,a2h,a3h, b0h,b1h);   // hi*hi
            mma_tf32(acc[nn], a0h,a1h,a2h,a3h, b0l,b1l);   // hi*lo
            mma_tf32(acc[nn], a0l,a1l,a2l,a3l, b0h,b1h);   // lo*hi
        }
    }

    // ---- epilogue: relu + blend ----
    float has0 = (v0 && g_cnt[r0] > 0) ? 1.f : 0.f;
    float has1 = (v1 && g_cnt[r1] > 0) ? 1.f : 0.f;
    #pragma unroll
    for (int nn = 0; nn < 16; nn++) {
        int col = nn * 8 + 2 * t4;
        float2 bj = *(const float2*)(bias + col);
        if (v0) {
            float2 xt = *(const float2*)(x_taste + (size_t)r0 * D + col);
            float2 o;
            o.x = fmaxf(has0 * (acc[nn][0] + bj.x), 0.f) * 0.5f + 0.5f * xt.x;
            o.y = fmaxf(has0 * (acc[nn][1] + bj.y), 0.f) * 0.5f + 0.5f * xt.y;
            *(float2*)(out_taste + (size_t)r0 * D + col) = o;
        }
        if (v1) {
            float2 xt = *(const float2*)(x_taste + (size_t)r1 * D + col);
            float2 o;
            o.x = fmaxf(has1 * (acc[nn][2] + bj.x), 0.f) * 0.5f + 0.5f * xt.x;
            o.y = fmaxf(has1 * (acc[nn][3] + bj.y), 0.f) * 0.5f + 0.5f * xt.y;
            *(float2*)(out_taste + (size_t)r1 * D + col) = o;
        }
    }
}

// ---------------- launcher (fork/join capture pattern) ----------------
extern "C" void kernel_launch(void* const* d_in, const int* in_sizes, int n_in,
                              void* d_out, int out_size) {
    const float* x_ing   = (const float*)d_in[0];
    const float* x_taste = (const float*)d_in[1];
    const float* W_ing   = (const float*)d_in[2];
    const float* b_ing   = (const float*)d_in[3];
    const float* W_taste = (const float*)d_in[4];
    const float* b_taste = (const float*)d_in[5];
    const float* att_src = (const float*)d_in[6];
    const float* att_dst = (const float*)d_in[7];
    // d_in[8..10] (Wk, bk, q): softmax over single metapath == 1.0 -> dead code
    const int* src_idx = (const int*)d_in[11];
    const int* dst_idx = (const int*)d_in[12];

    float* out       = (float*)d_out;
    float* out_ing   = out;                      // [N_ING, D] == x_ing
    float* out_taste = out + (size_t)N_ING * D;  // [N_TASTE, D]

    static const int SMEM_GEMM = D * SROW * (int)sizeof(float2);  // 135168

    static cudaStream_t sB = nullptr;
    static cudaEvent_t  evFork = nullptr, evFill = nullptr, evSplit = nullptr, evCopy = nullptr;
    if (sB == nullptr) {
        cudaStreamCreateWithFlags(&sB, cudaStreamNonBlocking);
        cudaEventCreateWithFlags(&evFork,  cudaEventDisableTiming);
        cudaEventCreateWithFlags(&evFill,  cudaEventDisableTiming);
        cudaEventCreateWithFlags(&evSplit, cudaEventDisableTiming);
        cudaEventCreateWithFlags(&evCopy,  cudaEventDisableTiming);
        cudaFuncSetAttribute(k_gemm, cudaFuncAttributeMaxDynamicSharedMemorySize, SMEM_GEMM);
    }

    // fork stream B: zero -> fill (CSR build), splitW, out_ing copy
    cudaEventRecord(evFork, 0);
    cudaStreamWaitEvent(sB, evFork, 0);
    k_zero<<<(N_TASTE + 1023) / 1024, 1024, 0, sB>>>();
    k_fill<<<(E_EDGES + 255) / 256, 256, 0, sB>>>(src_idx, dst_idx);
    cudaEventRecord(evFill, sB);
    k_splitW<<<(D * D + 255) / 256, 256, 0, sB>>>(W_ing);
    cudaEventRecord(evSplit, sB);
    k_copy<<<1024, 256, 0, sB>>>((const float4*)x_ing, (float4*)out_ing);
    cudaEventRecord(evCopy, sB);

    // stream A (default): k0 -> asrc -> agg -> gemm
    k0_prep<<<33, 256>>>(W_ing, b_ing, W_taste, b_taste, att_src, att_dst);
    k_asrc<<<3125, 256>>>(x_ing);                // 25000 warps = 100000 rows
    cudaStreamWaitEvent(0, evFill, 0);
    k_agg<<<6250, 256>>>(x_ing, x_taste);        // one dst per warp
    cudaStreamWaitEvent(0, evSplit, 0);
    k_gemm<<<(N_TASTE + TM - 1) / TM, 256, SMEM_GEMM>>>(b_ing, x_taste, out_taste);
    cudaStreamWaitEvent(0, evCopy, 0);           // join copy before graph end
}

// round 13
// speedup vs baseline: 1.0585x; 1.0585x over previous
#include <cuda_runtime.h>

#define D 128
#define N_ING 100000
#define N_TASTE 50000
#define E_EDGES 600000
#define NEG_SLOPE 0.2f
#define CAP 64          // per-dst bucket capacity; deg ~ Poisson(12), P(>64) < 1e-20

// ---------------- scratch (device globals) ----------------
__device__ float  g_v_src[D];
__device__ float  g_v_dst[D];
__device__ float  g_c_src, g_c_dst;
__device__ float  g_a_src[N_ING];
__device__ float  g_a_dst[N_TASTE];
__device__ int    g_cnt[N_TASTE];                  // degree cursor / epilogue mask
__device__ int2   g_slot[(size_t)N_TASTE * CAP];   // (src, exp-weight bits)
__device__ float2 g_wpk[D * D];                    // W packed (hi, lo) tf32 parts
__device__ float  g_gbuf[(size_t)N_TASTE * D];     // aggregated rows (25.6MB)

// ---------------- tf32 helpers ----------------
__device__ __forceinline__ void split_tf32(float x, unsigned& hi, unsigned& lo) {
    asm("cvt.rna.tf32.f32 %0, %1;" : "=r"(hi) : "f"(x));
    float lof = x - __uint_as_float(hi);
    asm("cvt.rna.tf32.f32 %0, %1;" : "=r"(lo) : "f"(lof));
}
__device__ __forceinline__ void mma_tf32(float* c,
                                         unsigned a0, unsigned a1, unsigned a2, unsigned a3,
                                         unsigned b0, unsigned b1) {
    asm volatile("mma.sync.aligned.m16n8k8.row.col.f32.tf32.tf32.f32 "
                 "{%0,%1,%2,%3}, {%4,%5,%6,%7}, {%8,%9}, {%0,%1,%2,%3};"
                 : "+f"(c[0]), "+f"(c[1]), "+f"(c[2]), "+f"(c[3])
                 : "r"(a0), "r"(a1), "r"(a2), "r"(a3), "r"(b0), "r"(b1));
}

// ---------------- K1: prep = (v vectors + bias dots) ∪ splitW --------------
// blocks [0,33): warp-per-row dots; blocks [33,97): W tf32 split
__global__ void k_prep(const float* __restrict__ W_ing,  const float* __restrict__ b_ing,
                       const float* __restrict__ W_taste,const float* __restrict__ b_taste,
                       const float* __restrict__ att_src,const float* __restrict__ att_dst) {
    if (blockIdx.x < 33) {
        int w    = (blockIdx.x * blockDim.x + threadIdx.x) >> 5;
        int lane = threadIdx.x & 31;
        if (w >= 258) return;
        const float* vecA;
        const float* vecB;
        if (w < 128)      { vecA = W_ing   + w * D;         vecB = att_src; }
        else if (w < 256) { vecA = W_taste + (w - 128) * D; vecB = att_dst; }
        else if (w == 256){ vecA = b_ing;                   vecB = att_src; }
        else              { vecA = b_taste;                 vecB = att_dst; }
        float4 a = ((const float4*)vecA)[lane];
        float4 c = ((const float4*)vecB)[lane];
        float s = a.x * c.x + a.y * c.y + a.z * c.z + a.w * c.w;
        #pragma unroll
        for (int o = 16; o; o >>= 1) s += __shfl_down_sync(0xffffffffu, s, o);
        if (lane == 0) {
            if (w < 128)       g_v_src[w] = s;
            else if (w < 256)  g_v_dst[w - 128] = s;
            else if (w == 256) g_c_src = s;
            else               g_c_dst = s;
        }
    } else {
        int i = (blockIdx.x - 33) * 256 + threadIdx.x;  // 64 blocks cover 16384
        if (i >= D * D) return;
        unsigned hi, lo;
        split_tf32(W_ing[i], hi, lo);
        g_wpk[i] = make_float2(__uint_as_float(hi), __uint_as_float(lo));
    }
}

// ---------------- K2: parallel bundle -------------------------------------
// blocks [0,3125):      out_ing copy + a_src (x_ing read once, 4 rows/warp)
// blocks [3125,4688):   a_dst (4 rows/warp)
// blocks [4688,4737):   zero g_cnt
#define PAR_ADST0 3125
#define PAR_ZERO0 4688
#define PAR_GRID  4737
__global__ void k_par(const float* __restrict__ x_ing, const float* __restrict__ x_taste,
                      float* __restrict__ out_ing) {
    int b = blockIdx.x;
    int lane = threadIdx.x & 31;
    int wrp  = threadIdx.x >> 5;
    if (b < PAR_ADST0) {
        int w = b * 8 + wrp;
        int row0 = w * 4;                          // exact: 25000 warps * 4 = 100000
        const float4* x4 = (const float4*)x_ing;
        float4* o4 = (float4*)out_ing;
        float4 vv = ((const float4*)g_v_src)[lane];
        float  cc = g_c_src;
        float4 xv[4];
        #pragma unroll
        for (int r = 0; r < 4; r++) xv[r] = x4[(size_t)(row0 + r) * 32 + lane];
        #pragma unroll
        for (int r = 0; r < 4; r++) {
            o4[(size_t)(row0 + r) * 32 + lane] = xv[r];
            float s = xv[r].x * vv.x + xv[r].y * vv.y + xv[r].z * vv.z + xv[r].w * vv.w;
            #pragma unroll
            for (int o = 16; o; o >>= 1) s += __shfl_down_sync(0xffffffffu, s, o);
            if (lane == 0) g_a_src[row0 + r] = s + cc;
        }
    } else if (b < PAR_ZERO0) {
        int w = (b - PAR_ADST0) * 8 + wrp;
        int row0 = w * 4;
        if (row0 >= N_TASTE) return;
        const float4* x4 = (const float4*)x_taste;
        float4 vv = ((const float4*)g_v_dst)[lane];
        float  cc = g_c_dst;
        float4 xv[4];
        #pragma unroll
        for (int r = 0; r < 4; r++) xv[r] = x4[(size_t)(row0 + r) * 32 + lane];
        #pragma unroll
        for (int r = 0; r < 4; r++) {
            float s = xv[r].x * vv.x + xv[r].y * vv.y + xv[r].z * vv.z + xv[r].w * vv.w;
            #pragma unroll
            for (int o = 16; o; o >>= 1) s += __shfl_down_sync(0xffffffffu, s, o);
            if (lane == 0) g_a_dst[row0 + r] = s + cc;
        }
    } else {
        for (int i = (b - PAR_ZERO0) * 256 + threadIdx.x; i < N_TASTE; i += 49 * 256)
            g_cnt[i] = 0;
    }
}

// ---------------- K3: fill buckets with (src, exp-weight) ------------------
__global__ void k_fill(const int* __restrict__ src, const int* __restrict__ dst) {
    int e = blockIdx.x * blockDim.x + threadIdx.x;
    if (e >= E_EDGES) return;
    int si = src[e];
    int t  = dst[e];
    float l = g_a_src[si] + g_a_dst[t];
    l = l > 0.f ? l : NEG_SLOPE * l;
    int pos = atomicAdd(&g_cnt[t], 1);          // pos < CAP w.h.p. (Poisson tail)
    g_slot[(size_t)t * CAP + pos] = make_int2(si, __float_as_int(__expf(l)));
}

// ---------------- K4: agg (warp per dst; weights inside slots) --------------
__global__ void __launch_bounds__(256) k_agg(const float* __restrict__ x_ing) {
    int gw    = (blockIdx.x * blockDim.x + threadIdx.x) >> 5;
    int lane  = threadIdx.x & 31;
    int nwarp = (gridDim.x * blockDim.x) >> 5;
    const float4* x4 = (const float4*)x_ing;
    float4* gb4 = (float4*)g_gbuf;
    for (int t = gw; t < N_TASTE; t += nwarp) {
        int n = g_cnt[t];
        const int2* sp = g_slot + (size_t)t * CAP;
        float4 acc = make_float4(0.f, 0.f, 0.f, 0.f);
        float wsum = 0.f;
        int e = 0;
        for (; e + 4 <= n; e += 4) {
            int2 e0 = sp[e], e1 = sp[e+1], e2 = sp[e+2], e3 = sp[e+3];
            float w0 = __int_as_float(e0.y), w1 = __int_as_float(e1.y);
            float w2 = __int_as_float(e2.y), w3 = __int_as_float(e3.y);
            float4 v0 = x4[(size_t)e0.x * 32 + lane];
            float4 v1 = x4[(size_t)e1.x * 32 + lane];
            float4 v2 = x4[(size_t)e2.x * 32 + lane];
            float4 v3 = x4[(size_t)e3.x * 32 + lane];
            wsum  += w0 + w1 + w2 + w3;
            acc.x += w0*v0.x + w1*v1.x + w2*v2.x + w3*v3.x;
            acc.y += w0*v0.y + w1*v1.y + w2*v2.y + w3*v3.y;
            acc.z += w0*v0.z + w1*v1.z + w2*v2.z + w3*v3.z;
            acc.w += w0*v0.w + w1*v1.w + w2*v2.w + w3*v3.w;
        }
        for (; e < n; e++) {
            int2 ee = sp[e];
            float w = __int_as_float(ee.y);
            float4 v = x4[(size_t)ee.x * 32 + lane];
            wsum += w;
            acc.x += w*v.x; acc.y += w*v.y; acc.z += w*v.z; acc.w += w*v.w;
        }
        float inv = 1.f / (wsum + 1e-16f);
        acc.x *= inv; acc.y *= inv; acc.z *= inv; acc.w *= inv;
        gb4[(size_t)t * 32 + lane] = acc;
    }
}

// ---------------- K5: TF32 3-pass MMA, packed W(hi,lo) in smem --------------
#define TM 128
#define SROW 132
__global__ void __launch_bounds__(256) k_gemm(const float* __restrict__ bias,
                                              const float* __restrict__ x_taste,
                                              float* __restrict__ out_taste) {
    extern __shared__ float2 wpk[];     // [128][SROW] packed (hi,lo)
    int tid  = threadIdx.x;
    int lane = tid & 31;
    int wrp  = tid >> 5;
    int row0 = blockIdx.x * TM;

    for (int i = tid; i < D * D; i += 256) {
        int k = i >> 7, n = i & 127;
        wpk[k * SROW + n] = g_wpk[i];
    }
    __syncthreads();

    int g = lane >> 2, t4 = lane & 3;
    int rbase = wrp * 16;
    int r0 = row0 + rbase + g;
    int r1 = r0 + 8;
    bool v0 = r0 < N_TASTE, v1 = r1 < N_TASTE;
    const float* A0 = g_gbuf + (size_t)(v0 ? r0 : 0) * D;
    const float* A1 = g_gbuf + (size_t)(v1 ? r1 : 0) * D;

    float acc[16][4];
    #pragma unroll
    for (int nn = 0; nn < 16; nn++)
        #pragma unroll
        for (int j = 0; j < 4; j++) acc[nn][j] = 0.f;

    #pragma unroll 1
    for (int kk = 0; kk < 16; kk++) {
        int k0 = kk * 8;
        float a0f = v0 ? A0[k0 + t4    ] : 0.f;
        float a2f = v0 ? A0[k0 + t4 + 4] : 0.f;
        float a1f = v1 ? A1[k0 + t4    ] : 0.f;
        float a3f = v1 ? A1[k0 + t4 + 4] : 0.f;
        unsigned a0h,a0l,a1h,a1l,a2h,a2l,a3h,a3l;
        split_tf32(a0f, a0h, a0l);
        split_tf32(a1f, a1h, a1l);
        split_tf32(a2f, a2h, a2l);
        split_tf32(a3f, a3h, a3l);
        #pragma unroll
        for (int nn = 0; nn < 16; nn++) {
            int col = nn * 8 + g;
            float2 b0 = wpk[(k0 + t4    ) * SROW + col];   // LDS.64: (hi, lo)
            float2 b1 = wpk[(k0 + t4 + 4) * SROW + col];
            unsigned b0h = __float_as_uint(b0.x), b0l = __float_as_uint(b0.y);
            unsigned b1h = __float_as_uint(b1.x), b1l = __float_as_uint(b1.y);
            mma_tf32(acc[nn], a0h,a1h,a2h,a3h, b0h,b1h);   // hi*hi
            mma_tf32(acc[nn], a0h,a1h,a2h,a3h, b0l,b1l);   // hi*lo
            mma_tf32(acc[nn], a0l,a1l,a2l,a3l, b0h,b1h);   // lo*hi
        }
    }

    float has0 = (v0 && g_cnt[r0] > 0) ? 1.f : 0.f;
    float has1 = (v1 && g_cnt[r1] > 0) ? 1.f : 0.f;
    #pragma unroll
    for (int nn = 0; nn < 16; nn++) {
        int col = nn * 8 + 2 * t4;
        float2 bj = *(const float2*)(bias + col);
        if (v0) {
            float2 xt = *(const float2*)(x_taste + (size_t)r0 * D + col);
            float2 o;
            o.x = fmaxf(has0 * (acc[nn][0] + bj.x), 0.f) * 0.5f + 0.5f * xt.x;
            o.y = fmaxf(has0 * (acc[nn][1] + bj.y), 0.f) * 0.5f + 0.5f * xt.y;
            *(float2*)(out_taste + (size_t)r0 * D + col) = o;
        }
        if (v1) {
            float2 xt = *(const float2*)(x_taste + (size_t)r1 * D + col);
            float2 o;
            o.x = fmaxf(has1 * (acc[nn][2] + bj.x), 0.f) * 0.5f + 0.5f * xt.x;
            o.y = fmaxf(has1 * (acc[nn][3] + bj.y), 0.f) * 0.5f + 0.5f * xt.y;
            *(float2*)(out_taste + (size_t)r1 * D + col) = o;
        }
    }
}

// ---------------- launcher: single stream, 5 kernels, 0 events -------------
extern "C" void kernel_launch(void* const* d_in, const int* in_sizes, int n_in,
                              void* d_out, int out_size) {
    const float* x_ing   = (const float*)d_in[0];
    const float* x_taste = (const float*)d_in[1];
    const float* W_ing   = (const float*)d_in[2];
    const float* b_ing   = (const float*)d_in[3];
    const float* W_taste = (const float*)d_in[4];
    const float* b_taste = (const float*)d_in[5];
    const float* att_src = (const float*)d_in[6];
    const float* att_dst = (const float*)d_in[7];
    // d_in[8..10] (Wk, bk, q): softmax over single metapath == 1.0 -> dead code
    const int* src_idx = (const int*)d_in[11];
    const int* dst_idx = (const int*)d_in[12];

    float* out       = (float*)d_out;
    float* out_ing   = out;                      // [N_ING, D] == x_ing
    float* out_taste = out + (size_t)N_ING * D;  // [N_TASTE, D]

    static const int SMEM_GEMM = D * SROW * (int)sizeof(float2);  // 135168
    static bool init = false;
    if (!init) {
        init = true;
        cudaFuncSetAttribute(k_gemm, cudaFuncAttributeMaxDynamicSharedMemorySize, SMEM_GEMM);
    }

    k_prep<<<97, 256>>>(W_ing, b_ing, W_taste, b_taste, att_src, att_dst);
    k_par<<<PAR_GRID, 256>>>(x_ing, x_taste, out_ing);
    k_fill<<<(E_EDGES + 255) / 256, 256>>>(src_idx, dst_idx);
    k_agg<<<6250, 256>>>(x_ing);
    k_gemm<<<(N_TASTE + TM - 1) / TM, 256, SMEM_GEMM>>>(b_ing, x_taste, out_taste);
}